// round 13
// baseline (speedup 1.0000x reference)
#include <cuda_runtime.h>
#include <cuda_bf16.h>
#include <cstdint>
#include <math.h>

#define NMAX 50048
#define FD   128
#define GG   64
#define TR   128
#define PAD  96
#define RS   272      // W smem row stride bytes
#define XRS  528      // X raw smem row stride bytes (132 floats)

// ---- static scratch ----
__device__ float d_bufA[NMAX * FD];
__device__ float d_bufB[NMAX * FD];
__device__ float d_gpool[GG * FD];
__device__ int   d_degi[NMAX];
__device__ int   d_ell[NMAX * PAD];
__device__ __nv_bfloat16 d_whi[2 * FD * FD];   // W^T hi, [layer][n][k]
__device__ __nv_bfloat16 d_wlo[2 * FD * FD];   // W^T lo

#define MMA(c, a, b) \
    asm volatile("mma.sync.aligned.m16n8k16.row.col.f32.bf16.bf16.f32 " \
        "{%0,%1,%2,%3},{%4,%5,%6,%7},{%8,%9},{%0,%1,%2,%3};" \
        : "+f"((c)[0]), "+f"((c)[1]), "+f"((c)[2]), "+f"((c)[3]) \
        : "r"((a)[0]), "r"((a)[1]), "r"((a)[2]), "r"((a)[3]), "r"((b)[0]), "r"((b)[1]))

__device__ __forceinline__ void cvt_hilo(float2 v, unsigned& h, unsigned& l) {
    __nv_bfloat16 h0 = __float2bfloat16_rn(v.x), h1 = __float2bfloat16_rn(v.y);
    __nv_bfloat16 l0 = __float2bfloat16_rn(v.x - __bfloat162float(h0));
    __nv_bfloat16 l1 = __float2bfloat16_rn(v.y - __bfloat162float(h1));
    h = ((unsigned)__bfloat16_as_ushort(h1) << 16) | __bfloat16_as_ushort(h0);
    l = ((unsigned)__bfloat16_as_ushort(l1) << 16) | __bfloat16_as_ushort(l0);
}

// ---------------- W prep ----------------
__global__ void prep_w(const float* __restrict__ W1, const float* __restrict__ W2,
                       __nv_bfloat16* __restrict__ whi, __nv_bfloat16* __restrict__ wlo) {
    int idx = blockIdx.x * blockDim.x + threadIdx.x;
    if (idx >= 32768) return;
    int layer = idx >> 14;
    int e = idx & 16383;
    int nn = e >> 7, k = e & 127;
    float w = (layer ? W2 : W1)[k * FD + nn];
    __nv_bfloat16 h = __float2bfloat16_rn(w);
    __nv_bfloat16 l = __float2bfloat16_rn(w - __bfloat162float(h));
    whi[idx] = h;
    wlo[idx] = l;
}

__global__ void zero_degi(int* __restrict__ degi, int n) {
    int i = blockIdx.x * blockDim.x + threadIdx.x;
    if (i < n) degi[i] = 0;
}

__global__ void fill_ell(const int* __restrict__ ei, int* __restrict__ degi,
                         int* __restrict__ ell, int E) {
    int i = blockIdx.x * blockDim.x + threadIdx.x;
    if (i >= E) return;
    int s = ei[i];
    int d = ei[E + i];
    int slot = atomicAdd(&degi[d], 1);
    if (slot < PAD) ell[(size_t)d * PAD + slot] = s;
}

// ---------------- persistent mma GEMM, 512 threads, double-buffered X ----------------
__device__ __forceinline__ void loadX_async(char* dst, const float* X, int row0, int n) {
    int rows = n - row0; if (rows > TR) rows = TR;
    #pragma unroll
    for (int it = 0; it < 8; it++) {
        int i = threadIdx.x + it * 512;      // float4 id in 128x32
        int r = i >> 5, c = i & 31;
        if (r < rows) {
            unsigned d = (unsigned)__cvta_generic_to_shared(dst + r * XRS + c * 16);
            const float4* g = (const float4*)X + (size_t)(row0 + r) * 32 + c;
            asm volatile("cp.async.cg.shared.global [%0], [%1], 16;" :: "r"(d), "l"(g));
        }
    }
}

__global__ void __launch_bounds__(512, 1)
gemm_mma(const float* __restrict__ X, const __nv_bfloat16* __restrict__ whi,
         const __nv_bfloat16* __restrict__ wlo, const int* __restrict__ degi,
         float* __restrict__ Y, int n, int ntiles) {
    extern __shared__ char sm[];
    char* Bhi = sm;                     // 34816
    char* Blo = sm + 34816;             // 34816
    char* X0  = sm + 69632;             // 67584
    char* X1  = sm + 137216;            // 67584 (total 204800)

    int tid = threadIdx.x;

    // W images (once per CTA)
    #pragma unroll
    for (int it = 0; it < 4; it++) {
        int i = tid + it * 512;
        int nn = i >> 4, c = i & 15;
        unsigned dh = (unsigned)__cvta_generic_to_shared(Bhi + nn * RS + c * 16);
        unsigned dl = (unsigned)__cvta_generic_to_shared(Blo + nn * RS + c * 16);
        asm volatile("cp.async.cg.shared.global [%0], [%1], 16;" :: "r"(dh), "l"((const char*)whi + (size_t)i * 16));
        asm volatile("cp.async.cg.shared.global [%0], [%1], 16;" :: "r"(dl), "l"((const char*)wlo + (size_t)i * 16));
    }
    asm volatile("cp.async.commit_group;" ::: "memory");

    if ((int)blockIdx.x < ntiles) loadX_async(X0, X, blockIdx.x * TR, n);
    asm volatile("cp.async.commit_group;" ::: "memory");

    int w = tid >> 5, lane = tid & 31;
    int gid = lane >> 2, tig = lane & 3;
    int mw = (w & 3) * 32;              // 4 warp-rows
    int nw = (w >> 2) * 32;             // 4 warp-cols

    int p = 0;
    for (int tile = blockIdx.x; tile < ntiles; tile += gridDim.x, p ^= 1) {
        char* cur = p ? X1 : X0;
        char* nxt = p ? X0 : X1;
        int nt = tile + gridDim.x;
        if (nt < ntiles) loadX_async(nxt, X, nt * TR, n);
        asm volatile("cp.async.commit_group;" ::: "memory");
        asm volatile("cp.async.wait_group 1;" ::: "memory");
        __syncthreads();

        float acc[2][4][4];
        #pragma unroll
        for (int t = 0; t < 2; t++)
            #pragma unroll
            for (int f = 0; f < 4; f++)
                #pragma unroll
                for (int q = 0; q < 4; q++) acc[t][f][q] = 0.f;

        #pragma unroll
        for (int ks = 0; ks < 8; ks++) {
            int k0 = ks * 16;
            unsigned ahi[2][4], alo[2][4], bh[4][2], bl[4][2];
            #pragma unroll
            for (int t = 0; t < 2; t++)
                #pragma unroll
                for (int rg = 0; rg < 4; rg++) {
                    int m = mw + t * 16 + gid + (rg & 1) * 8;
                    int kk = k0 + 2 * tig + (rg >> 1) * 8;
                    float2 v = *(const float2*)(cur + m * XRS + kk * 4);
                    cvt_hilo(v, ahi[t][rg], alo[t][rg]);
                }
            #pragma unroll
            for (int f = 0; f < 4; f++) {
                int nn = nw + f * 8 + gid;
                int kk = k0 + 2 * tig;
                bh[f][0] = *(const unsigned*)(Bhi + nn * RS + kk * 2);
                bh[f][1] = *(const unsigned*)(Bhi + nn * RS + kk * 2 + 16);
                bl[f][0] = *(const unsigned*)(Blo + nn * RS + kk * 2);
                bl[f][1] = *(const unsigned*)(Blo + nn * RS + kk * 2 + 16);
            }
            #pragma unroll
            for (int t = 0; t < 2; t++)
                #pragma unroll
                for (int f = 0; f < 4; f++) {
                    MMA(acc[t][f], ahi[t], bh[f]);
                    MMA(acc[t][f], ahi[t], bl[f]);
                    MMA(acc[t][f], alo[t], bh[f]);
                }
        }

        int row0 = tile * TR;
        #pragma unroll
        for (int t = 0; t < 2; t++) {
            int r0 = row0 + mw + t * 16 + gid;
            int r1 = r0 + 8;
            float s0 = (r0 < n) ? rsqrtf((float)(__ldg(&degi[r0]) + 1)) : 0.f;
            float s1 = (r1 < n) ? rsqrtf((float)(__ldg(&degi[r1]) + 1)) : 0.f;
            #pragma unroll
            for (int f = 0; f < 4; f++) {
                int col = nw + f * 8 + 2 * tig;
                if (r0 < n)
                    *(float2*)(Y + (size_t)r0 * FD + col) =
                        make_float2(acc[t][f][0] * s0, acc[t][f][1] * s0);
                if (r1 < n)
                    *(float2*)(Y + (size_t)r1 * FD + col) =
                        make_float2(acc[t][f][2] * s1, acc[t][f][3] * s1);
            }
        }
        __syncthreads();
    }
}

// ---------------- fused gather: warp per node, ELL, MLP=8 ----------------
__global__ void gather_fused(const float4* __restrict__ m4, const int* __restrict__ ell,
                             const int* __restrict__ degi, const float* __restrict__ bias,
                             float* __restrict__ hout, int n) {
    int gid = blockIdx.x * blockDim.x + threadIdx.x;
    int node = gid >> 5;
    if (node >= n) return;
    int lane = gid & 31;

    float4 acc = __ldg(&m4[(size_t)node * 32 + lane]);
    int deg_raw = __ldg(&degi[node]);
    int deg = deg_raw > PAD ? PAD : deg_raw;
    const int* row = ell + (size_t)node * PAD;

    int k = 0;
    for (; k + 8 <= deg; k += 8) {
        int u[8];
        #pragma unroll
        for (int t = 0; t < 8; t++) u[t] = __ldg(&row[k + t]);
        float4 v[8];
        #pragma unroll
        for (int t = 0; t < 8; t++) v[t] = __ldg(&m4[(size_t)u[t] * 32 + lane]);
        #pragma unroll
        for (int t = 0; t < 8; t++) {
            acc.x += v[t].x; acc.y += v[t].y; acc.z += v[t].z; acc.w += v[t].w;
        }
    }
    if (k + 4 <= deg) {
        int u[4];
        #pragma unroll
        for (int t = 0; t < 4; t++) u[t] = __ldg(&row[k + t]);
        float4 v[4];
        #pragma unroll
        for (int t = 0; t < 4; t++) v[t] = __ldg(&m4[(size_t)u[t] * 32 + lane]);
        #pragma unroll
        for (int t = 0; t < 4; t++) {
            acc.x += v[t].x; acc.y += v[t].y; acc.z += v[t].z; acc.w += v[t].w;
        }
        k += 4;
    }
    for (; k < deg; k++) {
        int u = __ldg(&row[k]);
        float4 v = __ldg(&m4[(size_t)u * 32 + lane]);
        acc.x += v.x; acc.y += v.y; acc.z += v.z; acc.w += v.w;
    }

    float dd = rsqrtf((float)(deg_raw + 1));
    float4 bb = ((const float4*)bias)[lane];
    float4 r;
    r.x = fmaxf(fmaf(acc.x, dd, bb.x), 0.f);
    r.y = fmaxf(fmaf(acc.y, dd, bb.y), 0.f);
    r.z = fmaxf(fmaf(acc.z, dd, bb.z), 0.f);
    r.w = fmaxf(fmaf(acc.w, dd, bb.w), 0.f);
    ((float4*)hout)[(size_t)node * 32 + lane] = r;
}

// ---------------- pool: one block per graph, zero atomics ----------------
__global__ void pool(const float* __restrict__ h, const int* __restrict__ batch,
                     float* __restrict__ gp, int n) {
    int g = blockIdx.x;
    int f = threadIdx.x;

    int lo = 0, hi = n;
    while (lo < hi) { int m = (lo + hi) >> 1; if (__ldg(&batch[m]) < g) lo = m + 1; else hi = m; }
    int s = lo;
    hi = n;
    while (lo < hi) { int m = (lo + hi) >> 1; if (__ldg(&batch[m]) < g + 1) lo = m + 1; else hi = m; }
    int e = lo;

    float m0 = 0.f, m1 = 0.f, m2 = 0.f, m3 = 0.f;
    int i = s;
    for (; i + 4 <= e; i += 4) {
        m0 = fmaxf(m0, __ldg(&h[(size_t)(i + 0) * FD + f]));
        m1 = fmaxf(m1, __ldg(&h[(size_t)(i + 1) * FD + f]));
        m2 = fmaxf(m2, __ldg(&h[(size_t)(i + 2) * FD + f]));
        m3 = fmaxf(m3, __ldg(&h[(size_t)(i + 3) * FD + f]));
    }
    for (; i < e; i++) m0 = fmaxf(m0, __ldg(&h[(size_t)i * FD + f]));
    gp[g * FD + f] = fmaxf(fmaxf(m0, m1), fmaxf(m2, m3));
}

// ---------------- head ----------------
__global__ void head(const float* __restrict__ g, const float* __restrict__ W3,
                     const float* __restrict__ b3, const float* __restrict__ W4,
                     const float* __restrict__ b4, float* __restrict__ out) {
    __shared__ float gs[FD];
    __shared__ float red0[4], red1[4];
    int r = blockIdx.x;
    int c = threadIdx.x;
    gs[c] = g[r * FD + c];
    __syncthreads();
    float acc = b3[c];
    #pragma unroll 8
    for (int k = 0; k < FD; k++)
        acc = fmaf(gs[k], W3[k * FD + c], acc);
    float z = acc > 0.f ? acc : 0.f;
    float p0 = z * W4[c * 2 + 0];
    float p1 = z * W4[c * 2 + 1];
    #pragma unroll
    for (int o = 16; o; o >>= 1) {
        p0 += __shfl_down_sync(0xffffffffu, p0, o);
        p1 += __shfl_down_sync(0xffffffffu, p1, o);
    }
    int wid = c >> 5;
    if ((c & 31) == 0) { red0[wid] = p0; red1[wid] = p1; }
    __syncthreads();
    if (c == 0) {
        float l0 = red0[0] + red0[1] + red0[2] + red0[3] + b4[0];
        float l1 = red1[0] + red1[1] + red1[2] + red1[3] + b4[1];
        float mx = fmaxf(l0, l1);
        float lse = mx + logf(expf(l0 - mx) + expf(l1 - mx));
        out[r * 2 + 0] = l0 - lse;
        out[r * 2 + 1] = l1 - lse;
    }
}

extern "C" void kernel_launch(void* const* d_in, const int* in_sizes, int n_in,
                              void* d_out, int out_size) {
    const float* x  = (const float*)d_in[0];
    const float* W1 = (const float*)d_in[1];
    const float* b1 = (const float*)d_in[2];
    const float* W2 = (const float*)d_in[3];
    const float* b2 = (const float*)d_in[4];
    const float* W3 = (const float*)d_in[5];
    const float* b3 = (const float*)d_in[6];
    const float* W4 = (const float*)d_in[7];
    const float* b4 = (const float*)d_in[8];
    const int*   ei = (const int*)d_in[9];
    const int* batch = (const int*)d_in[10];

    int n = in_sizes[0] / FD;
    int E = in_sizes[9] / 2;
    float* out = (float*)d_out;

    float *bufA, *bufB, *gp;
    int *degi, *ell;
    __nv_bfloat16 *whi, *wlo;
    cudaGetSymbolAddress((void**)&bufA, d_bufA);
    cudaGetSymbolAddress((void**)&bufB, d_bufB);
    cudaGetSymbolAddress((void**)&gp,   d_gpool);
    cudaGetSymbolAddress((void**)&degi, d_degi);
    cudaGetSymbolAddress((void**)&ell,  d_ell);
    cudaGetSymbolAddress((void**)&whi,  d_whi);
    cudaGetSymbolAddress((void**)&wlo,  d_wlo);

    static int sms = 0;
    if (sms == 0) {
        int dev = 0; cudaGetDevice(&dev);
        cudaDeviceGetAttribute(&sms, cudaDevAttrMultiProcessorCount, dev);
        if (sms <= 0) sms = 148;
    }

    const int smem = 204800;   // 200KB
    static int attr_set = 0;
    if (!attr_set) {
        cudaFuncSetAttribute(gemm_mma, cudaFuncAttributeMaxDynamicSharedMemorySize, smem);
        attr_set = 1;
    }

    int ntiles = (n + TR - 1) / TR;
    int gemm_grid = sms < ntiles ? sms : ntiles;
    int gather_blocks = (n * 32 + 255) / 256;

    prep_w<<<128, 256>>>(W1, W2, whi, wlo);                          // k1
    zero_degi<<<(n + 255) / 256, 256>>>(degi, n);                    // k2
    fill_ell<<<(E + 255) / 256, 256>>>(ei, degi, ell, E);            // k3

    // layer 1
    gemm_mma<<<gemm_grid, 512, smem>>>(x, whi, wlo, degi, bufA, n, ntiles); // k4 <- profiled
    gather_fused<<<gather_blocks, 256>>>((const float4*)bufA, ell, degi, b1, bufB, n); // k5
    // layer 2
    gemm_mma<<<gemm_grid, 512, smem>>>(bufB, whi + 16384, wlo + 16384, degi, bufA, n, ntiles); // k6
    gather_fused<<<gather_blocks, 256>>>((const float4*)bufA, ell, degi, b2, bufB, n); // k7

    pool<<<GG, FD>>>(bufB, batch, gp, n);                            // k8
    head<<<GG, FD>>>(gp, W3, b3, W4, b4, out);                       // k9
}

// round 14
// speedup vs baseline: 1.0438x; 1.0438x over previous
#include <cuda_runtime.h>
#include <cuda_bf16.h>
#include <cstdint>
#include <math.h>

#define NMAX 50048
#define FD   128
#define GG   64
#define TR   128
#define PAD  96
#define RS   272      // W smem row stride bytes
#define XRS  528      // X raw smem row stride bytes (132 floats)

// ---- static scratch ----
__device__ float d_bufA[NMAX * FD];
__device__ float d_bufB[NMAX * FD];
__device__ float d_gpool[GG * FD];
__device__ int   d_degi[NMAX];
__device__ int   d_ell[NMAX * PAD];
__device__ __nv_bfloat16 d_whi[2 * FD * FD];   // W^T hi, [layer][n][k]
__device__ __nv_bfloat16 d_wlo[2 * FD * FD];   // W^T lo

#define MMA(c, a, b) \
    asm volatile("mma.sync.aligned.m16n8k16.row.col.f32.bf16.bf16.f32 " \
        "{%0,%1,%2,%3},{%4,%5,%6,%7},{%8,%9},{%0,%1,%2,%3};" \
        : "+f"((c)[0]), "+f"((c)[1]), "+f"((c)[2]), "+f"((c)[3]) \
        : "r"((a)[0]), "r"((a)[1]), "r"((a)[2]), "r"((a)[3]), "r"((b)[0]), "r"((b)[1]))

// fast hi/lo: packed cvt for hi (RN), reconstruct, packed cvt for residual
__device__ __forceinline__ void cvt_hilo(float2 v, unsigned& h, unsigned& l) {
    unsigned hp;
    asm("cvt.rn.bf16x2.f32 %0, %1, %2;" : "=r"(hp) : "f"(v.y), "f"(v.x));
    float h0 = __uint_as_float(hp << 16);
    float h1 = __uint_as_float(hp & 0xFFFF0000u);
    unsigned lp;
    asm("cvt.rn.bf16x2.f32 %0, %1, %2;" : "=r"(lp) : "f"(v.y - h1), "f"(v.x - h0));
    h = hp; l = lp;
}

// ---------------- W prep + degi zero (fused) ----------------
__global__ void prep_w(const float* __restrict__ W1, const float* __restrict__ W2,
                       __nv_bfloat16* __restrict__ whi, __nv_bfloat16* __restrict__ wlo,
                       int* __restrict__ degi, int n) {
    int idx = blockIdx.x * blockDim.x + threadIdx.x;
    if (idx < 32768) {
        int layer = idx >> 14;
        int e = idx & 16383;
        int nn = e >> 7, k = e & 127;
        float w = (layer ? W2 : W1)[k * FD + nn];
        __nv_bfloat16 h = __float2bfloat16_rn(w);
        __nv_bfloat16 l = __float2bfloat16_rn(w - __bfloat162float(h));
        whi[idx] = h;
        wlo[idx] = l;
    }
    int di = idx - 32768;
    if (di >= 0 && di < n) degi[di] = 0;
}

__global__ void fill_ell(const int* __restrict__ ei, int* __restrict__ degi,
                         int* __restrict__ ell, int E) {
    int i = blockIdx.x * blockDim.x + threadIdx.x;
    if (i >= E) return;
    int s = ei[i];
    int d = ei[E + i];
    int slot = atomicAdd(&degi[d], 1);
    if (slot < PAD) ell[(size_t)d * PAD + slot] = s;
}

// ---------------- persistent mma GEMM, 256 threads, double-buffered X ----------------
__device__ __forceinline__ void loadX_async(char* dst, const float* X, int row0, int n) {
    int rows = n - row0; if (rows > TR) rows = TR;
    #pragma unroll
    for (int it = 0; it < 16; it++) {
        int i = threadIdx.x + it * 256;      // float4 id in 128x32
        int r = i >> 5, c = i & 31;
        if (r < rows) {
            unsigned d = (unsigned)__cvta_generic_to_shared(dst + r * XRS + c * 16);
            const float4* g = (const float4*)X + (size_t)(row0 + r) * 32 + c;
            asm volatile("cp.async.cg.shared.global [%0], [%1], 16;" :: "r"(d), "l"(g));
        }
    }
}

__global__ void __launch_bounds__(256, 1)
gemm_mma(const float* __restrict__ X, const __nv_bfloat16* __restrict__ whi,
         const __nv_bfloat16* __restrict__ wlo, const int* __restrict__ degi,
         float* __restrict__ Y, int n, int ntiles) {
    extern __shared__ char sm[];
    char* Bhi = sm;                     // 34816
    char* Blo = sm + 34816;             // 34816
    char* X0  = sm + 69632;             // 67584
    char* X1  = sm + 137216;            // 67584 (total 204800)

    int tid = threadIdx.x;

    // W images (once per CTA)
    #pragma unroll
    for (int it = 0; it < 8; it++) {
        int i = tid + it * 256;
        int nn = i >> 4, c = i & 15;
        unsigned dh = (unsigned)__cvta_generic_to_shared(Bhi + nn * RS + c * 16);
        unsigned dl = (unsigned)__cvta_generic_to_shared(Blo + nn * RS + c * 16);
        asm volatile("cp.async.cg.shared.global [%0], [%1], 16;" :: "r"(dh), "l"((const char*)whi + (size_t)i * 16));
        asm volatile("cp.async.cg.shared.global [%0], [%1], 16;" :: "r"(dl), "l"((const char*)wlo + (size_t)i * 16));
    }
    asm volatile("cp.async.commit_group;" ::: "memory");

    if ((int)blockIdx.x < ntiles) loadX_async(X0, X, blockIdx.x * TR, n);
    asm volatile("cp.async.commit_group;" ::: "memory");

    int w = tid >> 5, lane = tid & 31;
    int gid = lane >> 2, tig = lane & 3;
    int mw = (w & 3) * 32;
    int nw = (w >> 2) * 64;

    int p = 0;
    for (int tile = blockIdx.x; tile < ntiles; tile += gridDim.x, p ^= 1) {
        char* cur = p ? X1 : X0;
        char* nxt = p ? X0 : X1;
        int nt = tile + gridDim.x;
        if (nt < ntiles) loadX_async(nxt, X, nt * TR, n);
        asm volatile("cp.async.commit_group;" ::: "memory");
        asm volatile("cp.async.wait_group 1;" ::: "memory");
        __syncthreads();

        float acc[2][8][4];
        #pragma unroll
        for (int t = 0; t < 2; t++)
            #pragma unroll
            for (int f = 0; f < 8; f++)
                #pragma unroll
                for (int q = 0; q < 4; q++) acc[t][f][q] = 0.f;

        #pragma unroll
        for (int ks = 0; ks < 8; ks++) {
            int k0 = ks * 16;
            unsigned ahi[2][4], alo[2][4], bh[8][2], bl[8][2];
            #pragma unroll
            for (int t = 0; t < 2; t++)
                #pragma unroll
                for (int rg = 0; rg < 4; rg++) {
                    int m = mw + t * 16 + gid + (rg & 1) * 8;
                    int kk = k0 + 2 * tig + (rg >> 1) * 8;
                    float2 v = *(const float2*)(cur + m * XRS + kk * 4);
                    cvt_hilo(v, ahi[t][rg], alo[t][rg]);
                }
            #pragma unroll
            for (int f = 0; f < 8; f++) {
                int nn = nw + f * 8 + gid;
                int kk = k0 + 2 * tig;
                bh[f][0] = *(const unsigned*)(Bhi + nn * RS + kk * 2);
                bh[f][1] = *(const unsigned*)(Bhi + nn * RS + kk * 2 + 16);
                bl[f][0] = *(const unsigned*)(Blo + nn * RS + kk * 2);
                bl[f][1] = *(const unsigned*)(Blo + nn * RS + kk * 2 + 16);
            }
            #pragma unroll
            for (int t = 0; t < 2; t++)
                #pragma unroll
                for (int f = 0; f < 8; f++) {
                    MMA(acc[t][f], ahi[t], bh[f]);
                    MMA(acc[t][f], ahi[t], bl[f]);
                    MMA(acc[t][f], alo[t], bh[f]);
                }
        }

        int row0 = tile * TR;
        #pragma unroll
        for (int t = 0; t < 2; t++) {
            int r0 = row0 + mw + t * 16 + gid;
            int r1 = r0 + 8;
            float s0 = (r0 < n) ? rsqrtf((float)(__ldg(&degi[r0]) + 1)) : 0.f;
            float s1 = (r1 < n) ? rsqrtf((float)(__ldg(&degi[r1]) + 1)) : 0.f;
            #pragma unroll
            for (int f = 0; f < 8; f++) {
                int col = nw + f * 8 + 2 * tig;
                if (r0 < n)
                    *(float2*)(Y + (size_t)r0 * FD + col) =
                        make_float2(acc[t][f][0] * s0, acc[t][f][1] * s0);
                if (r1 < n)
                    *(float2*)(Y + (size_t)r1 * FD + col) =
                        make_float2(acc[t][f][2] * s1, acc[t][f][3] * s1);
            }
        }
        __syncthreads();
    }
}

// ---------------- fused gather: warp per node, ELL, MLP=8 ----------------
__global__ void gather_fused(const float4* __restrict__ m4, const int* __restrict__ ell,
                             const int* __restrict__ degi, const float* __restrict__ bias,
                             float* __restrict__ hout, int n) {
    int gid = blockIdx.x * blockDim.x + threadIdx.x;
    int node = gid >> 5;
    if (node >= n) return;
    int lane = gid & 31;

    float4 acc = __ldg(&m4[(size_t)node * 32 + lane]);
    int deg_raw = __ldg(&degi[node]);
    int deg = deg_raw > PAD ? PAD : deg_raw;
    const int* row = ell + (size_t)node * PAD;

    int k = 0;
    for (; k + 8 <= deg; k += 8) {
        int u[8];
        #pragma unroll
        for (int t = 0; t < 8; t++) u[t] = __ldg(&row[k + t]);
        float4 v[8];
        #pragma unroll
        for (int t = 0; t < 8; t++) v[t] = __ldg(&m4[(size_t)u[t] * 32 + lane]);
        #pragma unroll
        for (int t = 0; t < 8; t++) {
            acc.x += v[t].x; acc.y += v[t].y; acc.z += v[t].z; acc.w += v[t].w;
        }
    }
    if (k + 4 <= deg) {
        int u[4];
        #pragma unroll
        for (int t = 0; t < 4; t++) u[t] = __ldg(&row[k + t]);
        float4 v[4];
        #pragma unroll
        for (int t = 0; t < 4; t++) v[t] = __ldg(&m4[(size_t)u[t] * 32 + lane]);
        #pragma unroll
        for (int t = 0; t < 4; t++) {
            acc.x += v[t].x; acc.y += v[t].y; acc.z += v[t].z; acc.w += v[t].w;
        }
        k += 4;
    }
    for (; k < deg; k++) {
        int u = __ldg(&row[k]);
        float4 v = __ldg(&m4[(size_t)u * 32 + lane]);
        acc.x += v.x; acc.y += v.y; acc.z += v.z; acc.w += v.w;
    }

    float dd = rsqrtf((float)(deg_raw + 1));
    float4 bb = ((const float4*)bias)[lane];
    float4 r;
    r.x = fmaxf(fmaf(acc.x, dd, bb.x), 0.f);
    r.y = fmaxf(fmaf(acc.y, dd, bb.y), 0.f);
    r.z = fmaxf(fmaf(acc.z, dd, bb.z), 0.f);
    r.w = fmaxf(fmaf(acc.w, dd, bb.w), 0.f);
    ((float4*)hout)[(size_t)node * 32 + lane] = r;
}

// ---------------- pool: one block per graph, zero atomics ----------------
__global__ void pool(const float* __restrict__ h, const int* __restrict__ batch,
                     float* __restrict__ gp, int n) {
    int g = blockIdx.x;
    int f = threadIdx.x;

    int lo = 0, hi = n;
    while (lo < hi) { int m = (lo + hi) >> 1; if (__ldg(&batch[m]) < g) lo = m + 1; else hi = m; }
    int s = lo;
    hi = n;
    while (lo < hi) { int m = (lo + hi) >> 1; if (__ldg(&batch[m]) < g + 1) lo = m + 1; else hi = m; }
    int e = lo;

    float m0 = 0.f, m1 = 0.f, m2 = 0.f, m3 = 0.f;
    int i = s;
    for (; i + 4 <= e; i += 4) {
        m0 = fmaxf(m0, __ldg(&h[(size_t)(i + 0) * FD + f]));
        m1 = fmaxf(m1, __ldg(&h[(size_t)(i + 1) * FD + f]));
        m2 = fmaxf(m2, __ldg(&h[(size_t)(i + 2) * FD + f]));
        m3 = fmaxf(m3, __ldg(&h[(size_t)(i + 3) * FD + f]));
    }
    for (; i < e; i++) m0 = fmaxf(m0, __ldg(&h[(size_t)i * FD + f]));
    gp[g * FD + f] = fmaxf(fmaxf(m0, m1), fmaxf(m2, m3));
}

// ---------------- head ----------------
__global__ void head(const float* __restrict__ g, const float* __restrict__ W3,
                     const float* __restrict__ b3, const float* __restrict__ W4,
                     const float* __restrict__ b4, float* __restrict__ out) {
    __shared__ float gs[FD];
    __shared__ float red0[4], red1[4];
    int r = blockIdx.x;
    int c = threadIdx.x;
    gs[c] = g[r * FD + c];
    __syncthreads();
    float acc = b3[c];
    #pragma unroll 8
    for (int k = 0; k < FD; k++)
        acc = fmaf(gs[k], W3[k * FD + c], acc);
    float z = acc > 0.f ? acc : 0.f;
    float p0 = z * W4[c * 2 + 0];
    float p1 = z * W4[c * 2 + 1];
    #pragma unroll
    for (int o = 16; o; o >>= 1) {
        p0 += __shfl_down_sync(0xffffffffu, p0, o);
        p1 += __shfl_down_sync(0xffffffffu, p1, o);
    }
    int wid = c >> 5;
    if ((c & 31) == 0) { red0[wid] = p0; red1[wid] = p1; }
    __syncthreads();
    if (c == 0) {
        float l0 = red0[0] + red0[1] + red0[2] + red0[3] + b4[0];
        float l1 = red1[0] + red1[1] + red1[2] + red1[3] + b4[1];
        float mx = fmaxf(l0, l1);
        float lse = mx + logf(expf(l0 - mx) + expf(l1 - mx));
        out[r * 2 + 0] = l0 - lse;
        out[r * 2 + 1] = l1 - lse;
    }
}

extern "C" void kernel_launch(void* const* d_in, const int* in_sizes, int n_in,
                              void* d_out, int out_size) {
    const float* x  = (const float*)d_in[0];
    const float* W1 = (const float*)d_in[1];
    const float* b1 = (const float*)d_in[2];
    const float* W2 = (const float*)d_in[3];
    const float* b2 = (const float*)d_in[4];
    const float* W3 = (const float*)d_in[5];
    const float* b3 = (const float*)d_in[6];
    const float* W4 = (const float*)d_in[7];
    const float* b4 = (const float*)d_in[8];
    const int*   ei = (const int*)d_in[9];
    const int* batch = (const int*)d_in[10];

    int n = in_sizes[0] / FD;
    int E = in_sizes[9] / 2;
    float* out = (float*)d_out;

    float *bufA, *bufB, *gp;
    int *degi, *ell;
    __nv_bfloat16 *whi, *wlo;
    cudaGetSymbolAddress((void**)&bufA, d_bufA);
    cudaGetSymbolAddress((void**)&bufB, d_bufB);
    cudaGetSymbolAddress((void**)&gp,   d_gpool);
    cudaGetSymbolAddress((void**)&degi, d_degi);
    cudaGetSymbolAddress((void**)&ell,  d_ell);
    cudaGetSymbolAddress((void**)&whi,  d_whi);
    cudaGetSymbolAddress((void**)&wlo,  d_wlo);

    static int sms = 0;
    if (sms == 0) {
        int dev = 0; cudaGetDevice(&dev);
        cudaDeviceGetAttribute(&sms, cudaDevAttrMultiProcessorCount, dev);
        if (sms <= 0) sms = 148;
    }

    const int smem = 204800;   // 200KB
    static int attr_set = 0;
    if (!attr_set) {
        cudaFuncSetAttribute(gemm_mma, cudaFuncAttributeMaxDynamicSharedMemorySize, smem);
        attr_set = 1;
    }

    int ntiles = (n + TR - 1) / TR;
    int gemm_grid = sms < ntiles ? sms : ntiles;
    int gather_blocks = (n * 32 + 255) / 256;

    prep_w<<<(32768 + n + 255) / 256, 256>>>(W1, W2, whi, wlo, degi, n);   // k1 (zero fused)
    fill_ell<<<(E + 255) / 256, 256>>>(ei, degi, ell, E);                  // k2
    // dummy no-op slot shift not needed; profiled launch is #4 below
    // layer 1
    gemm_mma<<<gemm_grid, 256, smem>>>(x, whi, wlo, degi, bufA, n, ntiles); // k3
    gather_fused<<<gather_blocks, 256>>>((const float4*)bufA, ell, degi, b1, bufB, n); // k4 <- profiled
    // layer 2
    gemm_mma<<<gemm_grid, 256, smem>>>(bufB, whi + 16384, wlo + 16384, degi, bufA, n, ntiles); // k5
    gather_fused<<<gather_blocks, 256>>>((const float4*)bufA, ell, degi, b2, bufB, n); // k6

    pool<<<GG, FD>>>(bufB, batch, gp, n);                            // k7
    head<<<GG, FD>>>(gp, W3, b3, W4, b4, out);                       // k8
}

// round 15
// speedup vs baseline: 1.4061x; 1.3471x over previous
#include <cuda_runtime.h>
#include <cuda_bf16.h>
#include <cstdint>
#include <math.h>

#define NMAX 50048
#define FD   128
#define GG   64
#define TR   128
#define PAD  96
#define RS   272      // W smem row stride bytes
#define XRS  528      // X raw smem row stride bytes (132 floats)

// ---- static scratch ----
__device__ float d_bufA[NMAX * FD];
__device__ float d_bufB[NMAX * FD];
__device__ float d_gpool[GG * FD];
__device__ float d_dinv[NMAX];
__device__ int   d_degi[NMAX];
__device__ int   d_ell[NMAX * PAD];
__device__ __nv_bfloat16 d_whi[2 * FD * FD];   // W^T hi, [layer][n][k]
__device__ __nv_bfloat16 d_wlo[2 * FD * FD];   // W^T lo

#define MMA(c, a, b) \
    asm volatile("mma.sync.aligned.m16n8k16.row.col.f32.bf16.bf16.f32 " \
        "{%0,%1,%2,%3},{%4,%5,%6,%7},{%8,%9},{%0,%1,%2,%3};" \
        : "+f"((c)[0]), "+f"((c)[1]), "+f"((c)[2]), "+f"((c)[3]) \
        : "r"((a)[0]), "r"((a)[1]), "r"((a)[2]), "r"((a)[3]), "r"((b)[0]), "r"((b)[1]))

__device__ __forceinline__ void cvt_hilo(float2 v, unsigned& h, unsigned& l) {
    unsigned hp;
    asm("cvt.rn.bf16x2.f32 %0, %1, %2;" : "=r"(hp) : "f"(v.y), "f"(v.x));
    float h0 = __uint_as_float(hp << 16);
    float h1 = __uint_as_float(hp & 0xFFFF0000u);
    unsigned lp;
    asm("cvt.rn.bf16x2.f32 %0, %1, %2;" : "=r"(lp) : "f"(v.y - h1), "f"(v.x - h0));
    h = hp; l = lp;
}

// ---------------- W prep + gpool zero ----------------
__global__ void prep_w(const float* __restrict__ W1, const float* __restrict__ W2,
                       __nv_bfloat16* __restrict__ whi, __nv_bfloat16* __restrict__ wlo,
                       float* __restrict__ gp) {
    int idx = blockIdx.x * blockDim.x + threadIdx.x;
    if (idx < 32768) {
        int layer = idx >> 14;
        int e = idx & 16383;
        int nn = e >> 7, k = e & 127;
        float w = (layer ? W2 : W1)[k * FD + nn];
        __nv_bfloat16 h = __float2bfloat16_rn(w);
        __nv_bfloat16 l = __float2bfloat16_rn(w - __bfloat162float(h));
        whi[idx] = h;
        wlo[idx] = l;
    } else {
        int gi = idx - 32768;
        if (gi < GG * FD) gp[gi] = 0.f;
    }
}

__global__ void zero_degi(int* __restrict__ degi, int n) {
    int i = blockIdx.x * blockDim.x + threadIdx.x;
    if (i < n) degi[i] = 0;
}

__global__ void fill_ell(const int* __restrict__ ei, int* __restrict__ degi,
                         int* __restrict__ ell, int E) {
    int i = blockIdx.x * blockDim.x + threadIdx.x;
    if (i >= E) return;
    int s = ei[i];
    int d = ei[E + i];
    int slot = atomicAdd(&degi[d], 1);
    if (slot < PAD) ell[(size_t)d * PAD + slot] = s;
}

__global__ void dinv_from_deg(const int* __restrict__ degi, float* __restrict__ dinv, int n) {
    int i = blockIdx.x * blockDim.x + threadIdx.x;
    if (i < n) dinv[i] = rsqrtf((float)(degi[i] + 1));
}

// ---------------- persistent mma GEMM (pure X@W, no scaling) ----------------
__device__ __forceinline__ void loadX_async(char* dst, const float* X, int row0, int n) {
    int rows = n - row0; if (rows > TR) rows = TR;
    #pragma unroll
    for (int it = 0; it < 16; it++) {
        int i = threadIdx.x + it * 256;      // float4 id in 128x32
        int r = i >> 5, c = i & 31;
        if (r < rows) {
            unsigned d = (unsigned)__cvta_generic_to_shared(dst + r * XRS + c * 16);
            const float4* g = (const float4*)X + (size_t)(row0 + r) * 32 + c;
            asm volatile("cp.async.cg.shared.global [%0], [%1], 16;" :: "r"(d), "l"(g));
        }
    }
}

__global__ void __launch_bounds__(256, 1)
gemm_mma(const float* __restrict__ X, const __nv_bfloat16* __restrict__ whi,
         const __nv_bfloat16* __restrict__ wlo, float* __restrict__ Y, int n, int ntiles) {
    extern __shared__ char sm[];
    char* Bhi = sm;                     // 34816
    char* Blo = sm + 34816;             // 34816
    char* X0  = sm + 69632;             // 67584
    char* X1  = sm + 137216;            // 67584 (total 204800)

    int tid = threadIdx.x;

    #pragma unroll
    for (int it = 0; it < 8; it++) {
        int i = tid + it * 256;
        int nn = i >> 4, c = i & 15;
        unsigned dh = (unsigned)__cvta_generic_to_shared(Bhi + nn * RS + c * 16);
        unsigned dl = (unsigned)__cvta_generic_to_shared(Blo + nn * RS + c * 16);
        asm volatile("cp.async.cg.shared.global [%0], [%1], 16;" :: "r"(dh), "l"((const char*)whi + (size_t)i * 16));
        asm volatile("cp.async.cg.shared.global [%0], [%1], 16;" :: "r"(dl), "l"((const char*)wlo + (size_t)i * 16));
    }
    asm volatile("cp.async.commit_group;" ::: "memory");

    if ((int)blockIdx.x < ntiles) loadX_async(X0, X, blockIdx.x * TR, n);
    asm volatile("cp.async.commit_group;" ::: "memory");

    int w = tid >> 5, lane = tid & 31;
    int gid = lane >> 2, tig = lane & 3;
    int mw = (w & 3) * 32;
    int nw = (w >> 2) * 64;

    int p = 0;
    for (int tile = blockIdx.x; tile < ntiles; tile += gridDim.x, p ^= 1) {
        char* cur = p ? X1 : X0;
        char* nxt = p ? X0 : X1;
        int nt = tile + gridDim.x;
        if (nt < ntiles) loadX_async(nxt, X, nt * TR, n);
        asm volatile("cp.async.commit_group;" ::: "memory");
        asm volatile("cp.async.wait_group 1;" ::: "memory");
        __syncthreads();

        float acc[2][8][4];
        #pragma unroll
        for (int t = 0; t < 2; t++)
            #pragma unroll
            for (int f = 0; f < 8; f++)
                #pragma unroll
                for (int q = 0; q < 4; q++) acc[t][f][q] = 0.f;

        #pragma unroll
        for (int ks = 0; ks < 8; ks++) {
            int k0 = ks * 16;
            unsigned ahi[2][4], alo[2][4], bh[8][2], bl[8][2];
            #pragma unroll
            for (int t = 0; t < 2; t++)
                #pragma unroll
                for (int rg = 0; rg < 4; rg++) {
                    int m = mw + t * 16 + gid + (rg & 1) * 8;
                    int kk = k0 + 2 * tig + (rg >> 1) * 8;
                    float2 v = *(const float2*)(cur + m * XRS + kk * 4);
                    cvt_hilo(v, ahi[t][rg], alo[t][rg]);
                }
            #pragma unroll
            for (int f = 0; f < 8; f++) {
                int nn = nw + f * 8 + gid;
                int kk = k0 + 2 * tig;
                bh[f][0] = *(const unsigned*)(Bhi + nn * RS + kk * 2);
                bh[f][1] = *(const unsigned*)(Bhi + nn * RS + kk * 2 + 16);
                bl[f][0] = *(const unsigned*)(Blo + nn * RS + kk * 2);
                bl[f][1] = *(const unsigned*)(Blo + nn * RS + kk * 2 + 16);
            }
            #pragma unroll
            for (int t = 0; t < 2; t++)
                #pragma unroll
                for (int f = 0; f < 8; f++) {
                    MMA(acc[t][f], ahi[t], bh[f]);
                    MMA(acc[t][f], ahi[t], bl[f]);
                    MMA(acc[t][f], alo[t], bh[f]);
                }
        }

        int row0 = tile * TR;
        #pragma unroll
        for (int t = 0; t < 2; t++) {
            int r0 = row0 + mw + t * 16 + gid;
            int r1 = r0 + 8;
            #pragma unroll
            for (int f = 0; f < 8; f++) {
                int col = nw + f * 8 + 2 * tig;
                if (r0 < n)
                    *(float2*)(Y + (size_t)r0 * FD + col) =
                        make_float2(acc[t][f][0], acc[t][f][1]);
                if (r1 < n)
                    *(float2*)(Y + (size_t)r1 * FD + col) =
                        make_float2(acc[t][f][2], acc[t][f][3]);
            }
        }
        __syncthreads();
    }
}

// ---------------- fused gather: warp per node, ELL, per-edge dinv ----------------
__global__ void gather_fused(const float4* __restrict__ m4, const int* __restrict__ ell,
                             const int* __restrict__ degi, const float* __restrict__ dinv,
                             const float* __restrict__ bias, float* __restrict__ hout, int n) {
    int gid = blockIdx.x * blockDim.x + threadIdx.x;
    int node = gid >> 5;
    if (node >= n) return;
    int lane = gid & 31;

    float dself = __ldg(&dinv[node]);
    float4 sv = __ldg(&m4[(size_t)node * 32 + lane]);
    float4 acc;
    acc.x = sv.x * dself; acc.y = sv.y * dself;
    acc.z = sv.z * dself; acc.w = sv.w * dself;

    int deg_raw = __ldg(&degi[node]);
    int deg = deg_raw > PAD ? PAD : deg_raw;
    const int* row = ell + (size_t)node * PAD;

    int k = 0;
    for (; k + 8 <= deg; k += 8) {
        int u[8];
        #pragma unroll
        for (int t = 0; t < 8; t++) u[t] = __ldg(&row[k + t]);
        float ds[8];
        #pragma unroll
        for (int t = 0; t < 8; t++) ds[t] = __ldg(&dinv[u[t]]);
        float4 v[8];
        #pragma unroll
        for (int t = 0; t < 8; t++) v[t] = __ldg(&m4[(size_t)u[t] * 32 + lane]);
        #pragma unroll
        for (int t = 0; t < 8; t++) {
            acc.x = fmaf(ds[t], v[t].x, acc.x);
            acc.y = fmaf(ds[t], v[t].y, acc.y);
            acc.z = fmaf(ds[t], v[t].z, acc.z);
            acc.w = fmaf(ds[t], v[t].w, acc.w);
        }
    }
    if (k + 4 <= deg) {
        int u[4];
        #pragma unroll
        for (int t = 0; t < 4; t++) u[t] = __ldg(&row[k + t]);
        float ds[4];
        #pragma unroll
        for (int t = 0; t < 4; t++) ds[t] = __ldg(&dinv[u[t]]);
        float4 v[4];
        #pragma unroll
        for (int t = 0; t < 4; t++) v[t] = __ldg(&m4[(size_t)u[t] * 32 + lane]);
        #pragma unroll
        for (int t = 0; t < 4; t++) {
            acc.x = fmaf(ds[t], v[t].x, acc.x);
            acc.y = fmaf(ds[t], v[t].y, acc.y);
            acc.z = fmaf(ds[t], v[t].z, acc.z);
            acc.w = fmaf(ds[t], v[t].w, acc.w);
        }
        k += 4;
    }
    for (; k < deg; k++) {
        int u = __ldg(&row[k]);
        float dsv = __ldg(&dinv[u]);
        float4 v = __ldg(&m4[(size_t)u * 32 + lane]);
        acc.x = fmaf(dsv, v.x, acc.x);
        acc.y = fmaf(dsv, v.y, acc.y);
        acc.z = fmaf(dsv, v.z, acc.z);
        acc.w = fmaf(dsv, v.w, acc.w);
    }

    float4 bb = ((const float4*)bias)[lane];
    float4 r;
    r.x = fmaxf(fmaf(acc.x, dself, bb.x), 0.f);
    r.y = fmaxf(fmaf(acc.y, dself, bb.y), 0.f);
    r.z = fmaxf(fmaf(acc.z, dself, bb.z), 0.f);
    r.w = fmaxf(fmaf(acc.w, dself, bb.w), 0.f);
    ((float4*)hout)[(size_t)node * 32 + lane] = r;
}

// ---------------- pool: 8 blocks per graph + atomicMax (values >= 0) ----------------
__global__ void pool8(const float* __restrict__ h, const int* __restrict__ batch,
                      float* __restrict__ gp, int n) {
    int g = blockIdx.x >> 3;
    int part = blockIdx.x & 7;
    int f = threadIdx.x;

    int lo = 0, hi = n;
    while (lo < hi) { int m = (lo + hi) >> 1; if (__ldg(&batch[m]) < g) lo = m + 1; else hi = m; }
    int s = lo;
    hi = n;
    while (lo < hi) { int m = (lo + hi) >> 1; if (__ldg(&batch[m]) < g + 1) lo = m + 1; else hi = m; }
    int e = lo;

    int len = e - s;
    int chunk = (len + 7) >> 3;
    int ps = s + part * chunk;
    int pe = ps + chunk; if (pe > e) pe = e;
    if (ps >= pe) return;

    float m0 = 0.f, m1 = 0.f, m2 = 0.f, m3 = 0.f;
    int i = ps;
    for (; i + 4 <= pe; i += 4) {
        m0 = fmaxf(m0, __ldg(&h[(size_t)(i + 0) * FD + f]));
        m1 = fmaxf(m1, __ldg(&h[(size_t)(i + 1) * FD + f]));
        m2 = fmaxf(m2, __ldg(&h[(size_t)(i + 2) * FD + f]));
        m3 = fmaxf(m3, __ldg(&h[(size_t)(i + 3) * FD + f]));
    }
    for (; i < pe; i++) m0 = fmaxf(m0, __ldg(&h[(size_t)i * FD + f]));
    float m = fmaxf(fmaxf(m0, m1), fmaxf(m2, m3));
    atomicMax((int*)&gp[g * FD + f], __float_as_int(m));   // valid: m >= 0, gp init 0
}

// ---------------- head ----------------
__global__ void head(const float* __restrict__ g, const float* __restrict__ W3,
                     const float* __restrict__ b3, const float* __restrict__ W4,
                     const float* __restrict__ b4, float* __restrict__ out) {
    __shared__ float gs[FD];
    __shared__ float red0[4], red1[4];
    int r = blockIdx.x;
    int c = threadIdx.x;
    gs[c] = g[r * FD + c];
    __syncthreads();
    float acc = b3[c];
    #pragma unroll 8
    for (int k = 0; k < FD; k++)
        acc = fmaf(gs[k], W3[k * FD + c], acc);
    float z = acc > 0.f ? acc : 0.f;
    float p0 = z * W4[c * 2 + 0];
    float p1 = z * W4[c * 2 + 1];
    #pragma unroll
    for (int o = 16; o; o >>= 1) {
        p0 += __shfl_down_sync(0xffffffffu, p0, o);
        p1 += __shfl_down_sync(0xffffffffu, p1, o);
    }
    int wid = c >> 5;
    if ((c & 31) == 0) { red0[wid] = p0; red1[wid] = p1; }
    __syncthreads();
    if (c == 0) {
        float l0 = red0[0] + red0[1] + red0[2] + red0[3] + b4[0];
        float l1 = red1[0] + red1[1] + red1[2] + red1[3] + b4[1];
        float mx = fmaxf(l0, l1);
        float lse = mx + logf(expf(l0 - mx) + expf(l1 - mx));
        out[r * 2 + 0] = l0 - lse;
        out[r * 2 + 1] = l1 - lse;
    }
}

extern "C" void kernel_launch(void* const* d_in, const int* in_sizes, int n_in,
                              void* d_out, int out_size) {
    const float* x  = (const float*)d_in[0];
    const float* W1 = (const float*)d_in[1];
    const float* b1 = (const float*)d_in[2];
    const float* W2 = (const float*)d_in[3];
    const float* b2 = (const float*)d_in[4];
    const float* W3 = (const float*)d_in[5];
    const float* b3 = (const float*)d_in[6];
    const float* W4 = (const float*)d_in[7];
    const float* b4 = (const float*)d_in[8];
    const int*   ei = (const int*)d_in[9];
    const int* batch = (const int*)d_in[10];

    int n = in_sizes[0] / FD;
    int E = in_sizes[9] / 2;
    float* out = (float*)d_out;

    float *bufA, *bufB, *gp, *dinv;
    int *degi, *ell;
    __nv_bfloat16 *whi, *wlo;
    cudaGetSymbolAddress((void**)&bufA, d_bufA);
    cudaGetSymbolAddress((void**)&bufB, d_bufB);
    cudaGetSymbolAddress((void**)&gp,   d_gpool);
    cudaGetSymbolAddress((void**)&dinv, d_dinv);
    cudaGetSymbolAddress((void**)&degi, d_degi);
    cudaGetSymbolAddress((void**)&ell,  d_ell);
    cudaGetSymbolAddress((void**)&whi,  d_whi);
    cudaGetSymbolAddress((void**)&wlo,  d_wlo);

    static int sms = 0;
    static cudaStream_t sB = nullptr;
    static cudaEvent_t evF = nullptr, evJ = nullptr;
    if (sms == 0) {
        int dev = 0; cudaGetDevice(&dev);
        cudaDeviceGetAttribute(&sms, cudaDevAttrMultiProcessorCount, dev);
        if (sms <= 0) sms = 148;
        cudaStreamCreateWithFlags(&sB, cudaStreamNonBlocking);
        cudaEventCreateWithFlags(&evF, cudaEventDisableTiming);
        cudaEventCreateWithFlags(&evJ, cudaEventDisableTiming);
        cudaFuncSetAttribute(gemm_mma, cudaFuncAttributeMaxDynamicSharedMemorySize, 204800);
    }

    const int smem = 204800;
    int ntiles = (n + TR - 1) / TR;
    int gemm_grid = sms < ntiles ? sms : ntiles;
    int gather_blocks = (n * 32 + 255) / 256;

    // fork: graph prep (degi/ell/dinv) on stream B, overlapped with prep_w + gemm1
    cudaEventRecord(evF, 0);
    cudaStreamWaitEvent(sB, evF, 0);
    zero_degi<<<(n + 255) / 256, 256, 0, sB>>>(degi, n);
    fill_ell<<<(E + 255) / 256, 256, 0, sB>>>(ei, degi, ell, E);
    dinv_from_deg<<<(n + 255) / 256, 256, 0, sB>>>(degi, dinv, n);
    cudaEventRecord(evJ, sB);

    // main stream: W prep + gemm1 (independent of graph structure)
    prep_w<<<(32768 + GG * FD + 255) / 256, 256>>>(W1, W2, whi, wlo, gp);
    gemm_mma<<<gemm_grid, 256, smem>>>(x, whi, wlo, bufA, n, ntiles);

    // join, then the graph-dependent pipeline
    cudaStreamWaitEvent(0, evJ, 0);
    gather_fused<<<gather_blocks, 256>>>((const float4*)bufA, ell, degi, dinv, b1, bufB, n);
    gemm_mma<<<gemm_grid, 256, smem>>>(bufB, whi + 16384, wlo + 16384, bufA, n, ntiles);
    gather_fused<<<gather_blocks, 256>>>((const float4*)bufA, ell, degi, dinv, b2, bufB, n);

    pool8<<<GG * 8, FD>>>(bufB, batch, gp, n);
    head<<<GG, FD>>>(gp, W3, b3, W4, b4, out);
}